// round 12
// baseline (speedup 1.0000x reference)
#include <cuda_runtime.h>
#include <cstdint>

#define NHEADS   16
#define M_TBL    524288
#define D_IN     32
#define HID      64
#define NOUT     3
#define TILE     256
#define THREADS  512
#define NTILES   8192            // 8192 * 256 = 2,097,152
#define GRID     148             // persistent: 1 CTA (512 thr) per SM
#define STR      256

__constant__ __align__(16) float cW1[D_IN * HID];
__constant__ __align__(16) float cW2[HID * HID];
__constant__ __align__(16) float cW3[HID * HID];
__constant__ __align__(16) float cW4[HID * NOUT];
__constant__ __align__(16) float cb1[HID];
__constant__ __align__(16) float cb2[HID];
__constant__ __align__(16) float cb3[HID];
__constant__ __align__(16) float cb4[NOUT];

#define BUF_FLOATS (HID * STR)               // 16384 floats = 64 KB
#define SMEM_BYTES (2 * BUF_FLOATS * 4)      // 131072 -> 1 CTA/SM

#define FMA2(acc, a, w) \
    asm("fma.rn.f32x2 %0, %1, %2, %0;" : "+l"(acc) : "l"(a), "l"(w))
#define PACK2(d, s) \
    asm("mov.b64 %0, {%1, %1};" : "=l"(d) : "f"(s))
#define UNPACK2(lo, hi, s) \
    asm("mov.b64 {%0, %1}, %2;" : "=f"(lo), "=f"(hi) : "l"(s))

typedef unsigned long long ull;

// One layer, ping-pong: read A, write B (disjoint).
// Warp = (half, j-block): half = wid>>3 selects 128 points, jw = (wid&7)*8.
// Lane owns 4 points (hbase+lane4). acc[p*4 + jp] = j-pair (jw+2jp, jw+2jp+1).
// Per k-step: 1 LDS.128 + 2 LDC.128 + 4 PACK2 + 16 FFMA2.
template<int L, int K>
__device__ __forceinline__ void layer(const float* __restrict__ A,
                                      float* __restrict__ B,
                                      int jw, int hoff)   // hoff = half*128 + lane4
{
    ull acc[16];
    {
        ulonglong2 b01, b23;
        if constexpr (L == 1) {
            b01 = *reinterpret_cast<const ulonglong2*>(&cb1[jw]);
            b23 = *reinterpret_cast<const ulonglong2*>(&cb1[jw + 4]);
        } else if constexpr (L == 2) {
            b01 = *reinterpret_cast<const ulonglong2*>(&cb2[jw]);
            b23 = *reinterpret_cast<const ulonglong2*>(&cb2[jw + 4]);
        } else {
            b01 = *reinterpret_cast<const ulonglong2*>(&cb3[jw]);
            b23 = *reinterpret_cast<const ulonglong2*>(&cb3[jw + 4]);
        }
        #pragma unroll
        for (int p = 0; p < 4; p++) {
            acc[p*4 + 0] = b01.x; acc[p*4 + 1] = b01.y;
            acc[p*4 + 2] = b23.x; acc[p*4 + 3] = b23.y;
        }
    }

    #pragma unroll 8
    for (int k = 0; k < K; k++) {
        const float4 a = *reinterpret_cast<const float4*>(&A[k * STR + hoff]);
        ull d0, d1, d2, d3;
        PACK2(d0, a.x); PACK2(d1, a.y); PACK2(d2, a.z); PACK2(d3, a.w);

        ulonglong2 w01, w23;   // 4 natural j-pairs via 2 LDC.128 (warp-uniform)
        if constexpr (L == 1) {
            w01 = *reinterpret_cast<const ulonglong2*>(&cW1[k * HID + jw]);
            w23 = *reinterpret_cast<const ulonglong2*>(&cW1[k * HID + jw + 4]);
        } else if constexpr (L == 2) {
            w01 = *reinterpret_cast<const ulonglong2*>(&cW2[k * HID + jw]);
            w23 = *reinterpret_cast<const ulonglong2*>(&cW2[k * HID + jw + 4]);
        } else {
            w01 = *reinterpret_cast<const ulonglong2*>(&cW3[k * HID + jw]);
            w23 = *reinterpret_cast<const ulonglong2*>(&cW3[k * HID + jw + 4]);
        }

        FMA2(acc[ 0], d0, w01.x); FMA2(acc[ 1], d0, w01.y);
        FMA2(acc[ 2], d0, w23.x); FMA2(acc[ 3], d0, w23.y);
        FMA2(acc[ 4], d1, w01.x); FMA2(acc[ 5], d1, w01.y);
        FMA2(acc[ 6], d1, w23.x); FMA2(acc[ 7], d1, w23.y);
        FMA2(acc[ 8], d2, w01.x); FMA2(acc[ 9], d2, w01.y);
        FMA2(acc[10], d2, w23.x); FMA2(acc[11], d2, w23.y);
        FMA2(acc[12], d3, w01.x); FMA2(acc[13], d3, w01.y);
        FMA2(acc[14], d3, w23.x); FMA2(acc[15], d3, w23.y);
    }

    // relu + store 8 rows at this warp's half
    #pragma unroll
    for (int jp = 0; jp < 4; jp++) {
        float lo[4], hi[4];
        #pragma unroll
        for (int p = 0; p < 4; p++) {
            UNPACK2(lo[p], hi[p], acc[p*4 + jp]);
            lo[p] = fmaxf(lo[p], 0.0f);
            hi[p] = fmaxf(hi[p], 0.0f);
        }
        const int j0 = jw + 2 * jp;
        *reinterpret_cast<float4*>(&B[j0 * STR + hoff]) =
            make_float4(lo[0], lo[1], lo[2], lo[3]);
        *reinterpret_cast<float4*>(&B[(j0 + 1) * STR + hoff]) =
            make_float4(hi[0], hi[1], hi[2], hi[3]);
    }
}

__global__ __launch_bounds__(THREADS, 1)
void ngp_pp8_kernel(const int* __restrict__ idx,
                    const float* __restrict__ tables,
                    float* __restrict__ out)
{
    extern __shared__ float sm[];
    float* buf0 = sm;                 // input (rows 0..31) + L2 output
    float* buf1 = sm + BUF_FLOATS;    // L1, L3 outputs

    const int tid   = threadIdx.x;
    const int wid   = tid >> 5;
    const int lane  = tid & 31;
    const int jw    = (wid & 7) * 8;             // 8 j-cols per warp
    const int hoff  = (wid >> 3) * 128 + lane * 4; // point offset (half + lane)
    const int gp = tid >> 1;          // gather: point (2 threads/point)
    const int gh = (tid & 1) * 8;     // gather: head start

    // ---- gather first tile into buf0 rows 0..31 ----
    {
        const int* ip = idx + ((long)blockIdx.x * TILE + gp) * NHEADS + gh;
        const int4 i0 = *reinterpret_cast<const int4*>(ip);
        const int4 i1 = *reinterpret_cast<const int4*>(ip + 4);
        const int ii[8] = { i0.x, i0.y, i0.z, i0.w, i1.x, i1.y, i1.z, i1.w };
        #pragma unroll
        for (int i = 0; i < 8; i++) {
            const float2 v = *reinterpret_cast<const float2*>(
                tables + ((long)(gh + i) * M_TBL + ii[i]) * 2);
            buf0[(2 * (gh + i)    ) * STR + gp] = v.x;
            buf0[(2 * (gh + i) + 1) * STR + gp] = v.y;
        }
    }
    __syncthreads();

    for (long t = blockIdx.x; t < NTILES; t += GRID) {
        const long pbase = (long)t * TILE;
        const bool hasNext = (t + GRID) < NTILES;

        // idx LDG for NEXT tile (hidden under layer 1)
        int4 ni0 = make_int4(0,0,0,0), ni1 = make_int4(0,0,0,0);
        if (hasNext) {
            const int* ip = idx + ((t + GRID) * TILE + gp) * NHEADS + gh;
            ni0 = *reinterpret_cast<const int4*>(ip);
            ni1 = *reinterpret_cast<const int4*>(ip + 4);
        }

        // layer 1: buf0 -> buf1
        layer<1, D_IN>(buf0, buf1, jw, hoff);
        __syncthreads();                               // [1]

        // table LDGs for next tile (hidden under L2/L3)
        float2 nv[8];
        if (hasNext) {
            const int nii[8] = { ni0.x, ni0.y, ni0.z, ni0.w,
                                 ni1.x, ni1.y, ni1.z, ni1.w };
            #pragma unroll
            for (int i = 0; i < 8; i++)
                nv[i] = *reinterpret_cast<const float2*>(
                    tables + ((long)(gh + i) * M_TBL + nii[i]) * 2);
        }

        // layer 2: buf1 -> buf0
        layer<2, HID>(buf1, buf0, jw, hoff);
        __syncthreads();                               // [2]

        // layer 3: buf0 -> buf1
        layer<3, HID>(buf0, buf1, jw, hoff);
        __syncthreads();                               // [3]

        // buf0 is dead: park NEXT tile's gather (concurrent with L4)
        if (hasNext) {
            #pragma unroll
            for (int i = 0; i < 8; i++) {
                buf0[(2 * (gh + i)    ) * STR + gp] = nv[i].x;
                buf0[(2 * (gh + i) + 1) * STR + gp] = nv[i].y;
            }
        }

        // layer 4: buf1 -> out, 2 threads/point (k halves) + shfl combine
        {
            const int p  = tid >> 1;
            const int kb = (tid & 1) * 32;
            float o0 = 0.f, o1 = 0.f, o2 = 0.f;
            #pragma unroll 8
            for (int k = kb; k < kb + 32; k++) {
                const float a = buf1[k * STR + p];
                o0 = fmaf(a, cW4[k * NOUT + 0], o0);
                o1 = fmaf(a, cW4[k * NOUT + 1], o1);
                o2 = fmaf(a, cW4[k * NOUT + 2], o2);
            }
            o0 += __shfl_down_sync(0xFFFFFFFFu, o0, 1);
            o1 += __shfl_down_sync(0xFFFFFFFFu, o1, 1);
            o2 += __shfl_down_sync(0xFFFFFFFFu, o2, 1);
            if ((tid & 1) == 0) {
                float* op = out + (pbase + p) * NOUT;
                op[0] = o0 + cb4[0];
                op[1] = o1 + cb4[1];
                op[2] = o2 + cb4[2];
            }
        }
        __syncthreads();                               // [4]
    }
}

extern "C" void kernel_launch(void* const* d_in, const int* in_sizes, int n_in,
                              void* d_out, int out_size)
{
    static int init = 0;
    if (!init) {
        cudaFuncSetAttribute(ngp_pp8_kernel,
                             cudaFuncAttributeMaxDynamicSharedMemorySize,
                             SMEM_BYTES);
        init = 1;
    }

    cudaMemcpyToSymbolAsync(cW1, d_in[2], D_IN*HID*sizeof(float), 0,
                            cudaMemcpyDeviceToDevice, 0);
    cudaMemcpyToSymbolAsync(cb1, d_in[3], HID*sizeof(float), 0,
                            cudaMemcpyDeviceToDevice, 0);
    cudaMemcpyToSymbolAsync(cW2, d_in[4], HID*HID*sizeof(float), 0,
                            cudaMemcpyDeviceToDevice, 0);
    cudaMemcpyToSymbolAsync(cb2, d_in[5], HID*sizeof(float), 0,
                            cudaMemcpyDeviceToDevice, 0);
    cudaMemcpyToSymbolAsync(cW3, d_in[6], HID*HID*sizeof(float), 0,
                            cudaMemcpyDeviceToDevice, 0);
    cudaMemcpyToSymbolAsync(cb3, d_in[7], HID*sizeof(float), 0,
                            cudaMemcpyDeviceToDevice, 0);
    cudaMemcpyToSymbolAsync(cW4, d_in[8], HID*NOUT*sizeof(float), 0,
                            cudaMemcpyDeviceToDevice, 0);
    cudaMemcpyToSymbolAsync(cb4, d_in[9], NOUT*sizeof(float), 0,
                            cudaMemcpyDeviceToDevice, 0);

    ngp_pp8_kernel<<<GRID, THREADS, SMEM_BYTES>>>(
        (const int*)d_in[0], (const float*)d_in[1], (float*)d_out);
}